// round 2
// baseline (speedup 1.0000x reference)
#include <cuda_runtime.h>
#include <cuda_bf16.h>

#define K_DIM 1024
#define E_DIM 64
#define NVEC  (16 * 64 * 64)        // 65536 vectors
#define NPIX  (16 * 64 * 64 * 64)   // 4194304 output elements (vq part)
#define KC    128                   // codebook entries per shared-memory chunk

__device__ double d_loss_acc;
__device__ float  d_e2[K_DIM];

// ---- packed f32x2 helpers (sm_103a) ----
__device__ __forceinline__ void fma2(unsigned long long& d,
                                     unsigned long long a,
                                     unsigned long long b) {
    asm("fma.rn.f32x2 %0, %1, %2, %0;" : "+l"(d) : "l"(a), "l"(b));
}
__device__ __forceinline__ void add2(unsigned long long& d,
                                     unsigned long long a) {
    asm("add.rn.f32x2 %0, %0, %1;" : "+l"(d) : "l"(a));
}
__device__ __forceinline__ float2 unpack2(unsigned long long v) {
    float2 r;
    asm("mov.b64 {%0, %1}, %2;" : "=f"(r.x), "=f"(r.y) : "l"(v));
    return r;
}
__device__ __forceinline__ unsigned long long pack2(float lo, float hi) {
    unsigned long long v;
    asm("mov.b64 %0, {%1, %2};" : "=l"(v) : "f"(lo), "f"(hi));
    return v;
}

__global__ void init_kernel() { d_loss_acc = 0.0; }

// ||e_k||^2 for every codebook row (fp32, sequential order)
__global__ void e2_kernel(const float* __restrict__ cb) {
    int k = blockIdx.x * blockDim.x + threadIdx.x;
    if (k < K_DIM) {
        const float4* r = reinterpret_cast<const float4*>(cb + k * E_DIM);
        float s = 0.f;
#pragma unroll
        for (int i = 0; i < E_DIM / 4; i++) {
            float4 v = r[i];
            s += v.x * v.x + v.y * v.y + v.z * v.z + v.w * v.w;
        }
        d_e2[k] = s;
    }
}

__global__ __launch_bounds__(256, 2)
void vq_kernel(const float* __restrict__ z,
               const float* __restrict__ cb,
               float* __restrict__ out_vq) {
    __shared__ float sh_cb[KC * E_DIM];   // 32 KB
    __shared__ float sh_e2[KC];

    const int n   = blockIdx.x * 256 + threadIdx.x;   // vector id
    const int b   = n >> 12;                          // H*W = 4096
    const int hw  = n & 4095;
    const int base = b * (E_DIM * 4096) + hw;         // z[b, c, h, w] = z[base + c*4096]

    // Load this thread's z row (64 floats) into 32 packed f32x2 registers.
    // Coalesced: consecutive threads -> consecutive hw.
    unsigned long long zr[E_DIM / 2];
#pragma unroll
    for (int i = 0; i < E_DIM / 2; i++) {
        float lo = z[base + (2 * i)     * 4096];
        float hi = z[base + (2 * i + 1) * 4096];
        zr[i] = pack2(lo, hi);
    }

    // ||z||^2 in fp32. A uniform ulp offset vs the reference's reduction order
    // cancels in per-k comparisons; only the fp32 rounding STRUCTURE matters.
    float z2 = 0.f;
#pragma unroll
    for (int i = 0; i < E_DIM / 2; i++) {
        float2 v = unpack2(zr[i]);
        z2 = __fadd_rn(z2, __fadd_rn(__fmul_rn(v.x, v.x), __fmul_rn(v.y, v.y)));
    }

    float best = 3.4e38f;
    int   bidx = 0;

    for (int k0 = 0; k0 < K_DIM; k0 += KC) {
        __syncthreads();
        // Cooperative load of KC x 64 floats = 8192 floats (8 float4 per thread)
        const float4* src = reinterpret_cast<const float4*>(cb + k0 * E_DIM);
        float4* dst = reinterpret_cast<float4*>(sh_cb);
#pragma unroll
        for (int i = 0; i < (KC * E_DIM / 4) / 256; i++)
            dst[threadIdx.x + i * 256] = src[threadIdx.x + i * 256];
        if (threadIdx.x < KC) sh_e2[threadIdx.x] = d_e2[k0 + threadIdx.x];
        __syncthreads();

#pragma unroll 1
        for (int j = 0; j < KC; j++) {
            const ulonglong2* ep =
                reinterpret_cast<const ulonglong2*>(sh_cb + j * E_DIM);
            unsigned long long a0 = 0ull, a1 = 0ull, a2 = 0ull, a3 = 0ull;
#pragma unroll
            for (int i = 0; i < 8; i++) {          // 16x LDS.128, 32x FFMA2
                ulonglong2 e0 = ep[2 * i];
                ulonglong2 e1 = ep[2 * i + 1];
                fma2(a0, zr[4 * i + 0], e0.x);
                fma2(a1, zr[4 * i + 1], e0.y);
                fma2(a2, zr[4 * i + 2], e1.x);
                fma2(a3, zr[4 * i + 3], e1.y);
            }
            add2(a0, a1);
            add2(a2, a3);
            add2(a0, a2);
            float2 s = unpack2(a0);
            float dot = __fadd_rn(s.x, s.y);
            // Replicate reference fp32 rounding: (z2 + e2) - 2*dot.
            // The large z2 anchor quantizes comparisons to its ~7.6e-6 ulp grid;
            // exact fp32 ties then break to the LOWEST k (strict <, ascending j),
            // matching jnp.argmin's first-occurrence rule.
            float t    = __fadd_rn(z2, sh_e2[j]);
            float dist = __fsub_rn(t, __fmul_rn(2.0f, dot));
            if (dist < best) { best = dist; bidx = k0 + j; }
        }
    }

    // Epilogue: gather winning codebook row (L2-resident), write vq (straight-through
    // value == vq), accumulate loss = sum (vq - z)^2.
    const float2* er = reinterpret_cast<const float2*>(cb + bidx * E_DIM);
    float local = 0.f;
#pragma unroll
    for (int i = 0; i < E_DIM / 2; i++) {
        float2 e  = __ldg(&er[i]);
        float2 zp = unpack2(zr[i]);
        float d0 = e.x - zp.x, d1 = e.y - zp.y;
        local += d0 * d0 + d1 * d1;
        out_vq[base + (2 * i)     * 4096] = e.x;
        out_vq[base + (2 * i + 1) * 4096] = e.y;
    }

    // warp reduce + one double atomic per warp
#pragma unroll
    for (int o = 16; o; o >>= 1)
        local += __shfl_xor_sync(0xFFFFFFFFu, local, o);
    if ((threadIdx.x & 31) == 0)
        atomicAdd(&d_loss_acc, (double)local);
}

__global__ void fin_kernel(float* out, int has_loss) {
    if (has_loss)
        out[0] = (float)(1.25 * d_loss_acc / (double)NPIX);
}

extern "C" void kernel_launch(void* const* d_in, const int* in_sizes, int n_in,
                              void* d_out, int out_size) {
    // metadata order: z [16,64,64,64] fp32, codebook [1024,64] fp32.
    const float* z  = (const float*)d_in[0];
    const float* cb = (const float*)d_in[1];
    if (n_in >= 2 && in_sizes[0] == K_DIM * E_DIM && in_sizes[1] == NPIX) {
        // defensive: inputs swapped
        const float* t = z; z = cb; cb = t;
    }

    float* out = (float*)d_out;
    int voff = out_size - NPIX;            // 1 if scalar loss precedes vq_out
    if (voff < 0) voff = 0;
    float* out_vq = out + voff;

    init_kernel<<<1, 1>>>();
    e2_kernel<<<K_DIM / 256, 256>>>(cb);
    vq_kernel<<<NVEC / 256, 256>>>(z, cb, out_vq);
    fin_kernel<<<1, 1>>>(out, voff > 0 ? 1 : 0);
}

// round 3
// speedup vs baseline: 1.2052x; 1.2052x over previous
#include <cuda_runtime.h>
#include <cuda_bf16.h>

#define K_DIM 1024
#define E_DIM 64
#define NVEC  (16 * 64 * 64)        // 65536 vectors
#define NPIX  (16 * 64 * 64 * 64)   // 4194304 output elements (vq part)
#define KC    128                   // codebook entries per shared-memory chunk

__device__ double d_loss_acc;
__device__ float  d_e2[K_DIM];

// ---- packed f32x2 helpers (sm_103a) ----
__device__ __forceinline__ void fma2(unsigned long long& d,
                                     unsigned long long a,
                                     unsigned long long b) {
    asm("fma.rn.f32x2 %0, %1, %2, %0;" : "+l"(d) : "l"(a), "l"(b));
}
__device__ __forceinline__ void add2(unsigned long long& d,
                                     unsigned long long a) {
    asm("add.rn.f32x2 %0, %0, %1;" : "+l"(d) : "l"(a));
}
__device__ __forceinline__ float2 unpack2(unsigned long long v) {
    float2 r;
    asm("mov.b64 {%0, %1}, %2;" : "=f"(r.x), "=f"(r.y) : "l"(v));
    return r;
}
__device__ __forceinline__ unsigned long long pack2(float lo, float hi) {
    unsigned long long v;
    asm("mov.b64 %0, {%1, %2};" : "=l"(v) : "f"(lo), "f"(hi));
    return v;
}

__global__ void init_kernel() { d_loss_acc = 0.0; }

// ||e_k||^2 for every codebook row (fp32, sequential order)
__global__ void e2_kernel(const float* __restrict__ cb) {
    int k = blockIdx.x * blockDim.x + threadIdx.x;
    if (k < K_DIM) {
        const float4* r = reinterpret_cast<const float4*>(cb + k * E_DIM);
        float s = 0.f;
#pragma unroll
        for (int i = 0; i < E_DIM / 4; i++) {
            float4 v = r[i];
            s += v.x * v.x + v.y * v.y + v.z * v.z + v.w * v.w;
        }
        d_e2[k] = s;
    }
}

// T=2 z-vectors per thread: the broadcast codebook row (16x LDS.128 per j)
// is amortized over 64 FFMA2 instead of 32, relieving the LSU 4-cyc floor
// that was co-critical with the fma pipe in round 2.
__global__ __launch_bounds__(128, 2)
void vq_kernel(const float* __restrict__ z,
               const float* __restrict__ cb,
               float* __restrict__ out_vq) {
    __shared__ float sh_cb[KC * E_DIM];   // 32 KB
    __shared__ float sh_e2[KC];

    const int tid = threadIdx.x;
    const int n0  = blockIdx.x * 256 + tid;     // vector ids n0 and n0+128
    const int n1  = n0 + 128;
    const int b0  = n0 >> 12, hw0 = n0 & 4095;
    const int b1  = n1 >> 12, hw1 = n1 & 4095;
    const int base0 = b0 * (E_DIM * 4096) + hw0;   // z[b,c,h,w] = z[base + c*4096]
    const int base1 = b1 * (E_DIM * 4096) + hw1;

    // Both z rows in registers as packed f32x2 (64 regs each).
    unsigned long long zr0[E_DIM / 2], zr1[E_DIM / 2];
#pragma unroll
    for (int i = 0; i < E_DIM / 2; i++) {
        zr0[i] = pack2(z[base0 + (2 * i) * 4096], z[base0 + (2 * i + 1) * 4096]);
        zr1[i] = pack2(z[base1 + (2 * i) * 4096], z[base1 + (2 * i + 1) * 4096]);
    }

    // ||z||^2 in fp32, sequential pair order (rounding STRUCTURE is what must
    // match the reference's z2-anchored comparison grid; uniform ulp offsets
    // cancel across k).
    float z20 = 0.f, z21 = 0.f;
#pragma unroll
    for (int i = 0; i < E_DIM / 2; i++) {
        float2 v0 = unpack2(zr0[i]);
        float2 v1 = unpack2(zr1[i]);
        z20 = __fadd_rn(z20, __fadd_rn(__fmul_rn(v0.x, v0.x), __fmul_rn(v0.y, v0.y)));
        z21 = __fadd_rn(z21, __fadd_rn(__fmul_rn(v1.x, v1.x), __fmul_rn(v1.y, v1.y)));
    }

    float best0 = 3.4e38f, best1 = 3.4e38f;
    int   bidx0 = 0,       bidx1 = 0;

    for (int k0 = 0; k0 < K_DIM; k0 += KC) {
        __syncthreads();
        // Cooperative load: KC*64 floats = 2048 float4 / 128 threads = 16 each
        const float4* src = reinterpret_cast<const float4*>(cb + k0 * E_DIM);
        float4* dst = reinterpret_cast<float4*>(sh_cb);
#pragma unroll
        for (int i = 0; i < (KC * E_DIM / 4) / 128; i++)
            dst[tid + i * 128] = src[tid + i * 128];
        sh_e2[tid] = d_e2[k0 + tid];              // KC == blockDim
        __syncthreads();

#pragma unroll 1
        for (int j = 0; j < KC; j++) {
            const ulonglong2* ep =
                reinterpret_cast<const ulonglong2*>(sh_cb + j * E_DIM);
            unsigned long long a0 = 0ull, a1 = 0ull, a2 = 0ull, a3 = 0ull;
            unsigned long long b0a = 0ull, b1a = 0ull, b2a = 0ull, b3a = 0ull;
#pragma unroll
            for (int i = 0; i < 8; i++) {          // 16x LDS.128 shared by 64 FFMA2
                ulonglong2 e0 = ep[2 * i];
                ulonglong2 e1 = ep[2 * i + 1];
                fma2(a0,  zr0[4 * i + 0], e0.x);
                fma2(b0a, zr1[4 * i + 0], e0.x);
                fma2(a1,  zr0[4 * i + 1], e0.y);
                fma2(b1a, zr1[4 * i + 1], e0.y);
                fma2(a2,  zr0[4 * i + 2], e1.x);
                fma2(b2a, zr1[4 * i + 2], e1.x);
                fma2(a3,  zr0[4 * i + 3], e1.y);
                fma2(b3a, zr1[4 * i + 3], e1.y);
            }
            add2(a0, a1);   add2(b0a, b1a);
            add2(a2, a3);   add2(b2a, b3a);
            add2(a0, a2);   add2(b0a, b2a);
            float2 s0 = unpack2(a0);
            float2 s1 = unpack2(b0a);
            float dot0 = __fadd_rn(s0.x, s0.y);
            float dot1 = __fadd_rn(s1.x, s1.y);
            // Reference fp32 rounding: (z2 + e2) - 2*dot. 2*dot is exact, so
            // fma(-2, dot, t) == fsub(t, 2*dot) bit-for-bit (single rounding).
            float e2j = sh_e2[j];
            float d0 = __fmaf_rn(-2.0f, dot0, __fadd_rn(z20, e2j));
            float d1 = __fmaf_rn(-2.0f, dot1, __fadd_rn(z21, e2j));
            bool l0 = d0 < best0;                  // strict <: first-occurrence
            bool l1 = d1 < best1;
            best0 = l0 ? d0 : best0;  bidx0 = l0 ? (k0 + j) : bidx0;
            best1 = l1 ? d1 : best1;  bidx1 = l1 ? (k0 + j) : bidx1;
        }
    }

    // Epilogue: gather winning rows (L2-resident), write vq, accumulate loss.
    float local = 0.f;
    {
        const float2* er = reinterpret_cast<const float2*>(cb + bidx0 * E_DIM);
#pragma unroll
        for (int i = 0; i < E_DIM / 2; i++) {
            float2 e  = __ldg(&er[i]);
            float2 zp = unpack2(zr0[i]);
            float q0 = e.x - zp.x, q1 = e.y - zp.y;
            local += q0 * q0 + q1 * q1;
            out_vq[base0 + (2 * i)     * 4096] = e.x;
            out_vq[base0 + (2 * i + 1) * 4096] = e.y;
        }
    }
    {
        const float2* er = reinterpret_cast<const float2*>(cb + bidx1 * E_DIM);
#pragma unroll
        for (int i = 0; i < E_DIM / 2; i++) {
            float2 e  = __ldg(&er[i]);
            float2 zp = unpack2(zr1[i]);
            float q0 = e.x - zp.x, q1 = e.y - zp.y;
            local += q0 * q0 + q1 * q1;
            out_vq[base1 + (2 * i)     * 4096] = e.x;
            out_vq[base1 + (2 * i + 1) * 4096] = e.y;
        }
    }

    // warp reduce + one double atomic per warp
#pragma unroll
    for (int o = 16; o; o >>= 1)
        local += __shfl_xor_sync(0xFFFFFFFFu, local, o);
    if ((tid & 31) == 0)
        atomicAdd(&d_loss_acc, (double)local);
}

__global__ void fin_kernel(float* out, int has_loss) {
    if (has_loss)
        out[0] = (float)(1.25 * d_loss_acc / (double)NPIX);
}

extern "C" void kernel_launch(void* const* d_in, const int* in_sizes, int n_in,
                              void* d_out, int out_size) {
    // metadata order: z [16,64,64,64] fp32, codebook [1024,64] fp32.
    const float* z  = (const float*)d_in[0];
    const float* cb = (const float*)d_in[1];
    if (n_in >= 2 && in_sizes[0] == K_DIM * E_DIM && in_sizes[1] == NPIX) {
        const float* t = z; z = cb; cb = t;   // defensive: inputs swapped
    }

    float* out = (float*)d_out;
    int voff = out_size - NPIX;            // 1 if scalar loss precedes vq_out
    if (voff < 0) voff = 0;
    float* out_vq = out + voff;

    init_kernel<<<1, 1>>>();
    e2_kernel<<<K_DIM / 256, 256>>>(cb);
    vq_kernel<<<NVEC / 256, 128>>>(z, cb, out_vq);   // 2 vectors per thread
    fin_kernel<<<1, 1>>>(out, voff > 0 ? 1 : 0);
}